// round 1
// baseline (speedup 1.0000x reference)
#include <cuda_runtime.h>
#include <cuda_bf16.h>
#include <math.h>

// ---------------- problem constants ----------------
#define N_EMBD   1024
#define D_INNER  2048
#define D_STATE  64
#define N_HEADS  32
#define HEAD_DIM 64
#define D_CONV   4
#define SEQ      512
#define PROJ     4256          // 2*D_INNER + N_HEADS + 2*D_STATE
#define COL_GATE 0
#define COL_SSM  2048
#define COL_DT   4096
#define COL_B    4128
#define COL_C    4192

// ---------------- scratch (no allocation allowed) ----------------
__device__ float g_xn  [SEQ * N_EMBD];
__device__ float g_proj[SEQ * PROJ];
__device__ float g_h   [SEQ * D_INNER];
__device__ float g_dt  [N_HEADS * SEQ];   // [h][t]
__device__ float g_la  [N_HEADS * SEQ];   // [h][t] inclusive cumsum of A*dt
__device__ float g_G   [SEQ * SEQ];       // C @ B^T
__device__ float g_y   [SEQ * D_INNER];

__device__ __forceinline__ float siluf(float v) {
    return v / (1.0f + expf(-v));
}

// ---------------- RMSNorm ----------------
__global__ void rmsnorm_kernel(const float* __restrict__ x,
                               const float* __restrict__ scale,
                               float* __restrict__ out) {
    int row = blockIdx.x;
    int tid = threadIdx.x;              // 256 threads, 1 float4 each
    const float4* xr = reinterpret_cast<const float4*>(x + row * N_EMBD);
    float4 v = xr[tid];
    float ss = v.x * v.x + v.y * v.y + v.z * v.z + v.w * v.w;
    #pragma unroll
    for (int o = 16; o; o >>= 1) ss += __shfl_xor_sync(0xffffffffu, ss, o);
    __shared__ float wsum[8];
    int lane = tid & 31, wid = tid >> 5;
    if (lane == 0) wsum[wid] = ss;
    __syncthreads();
    __shared__ float s_inv;
    if (tid == 0) {
        float tot = 0.f;
        #pragma unroll
        for (int i = 0; i < 8; i++) tot += wsum[i];
        s_inv = rsqrtf(tot / (float)N_EMBD + 1e-6f);
    }
    __syncthreads();
    float inv = s_inv;
    const float4 sc = reinterpret_cast<const float4*>(scale)[tid];
    float4 o;
    o.x = v.x * inv * sc.x;  o.y = v.y * inv * sc.y;
    o.z = v.z * inv * sc.z;  o.w = v.w * inv * sc.w;
    reinterpret_cast<float4*>(out + row * N_EMBD)[tid] = o;
}

// ---------------- generic register-tiled SGEMM ----------------
// C[M,N] = A[M,K] @ B[K,N], all row-major.  M % BM == 0, K % BK == 0 assumed.
// N guarded (per float4 since N % 4 == 0).  Optional residual add.
template<int BM, int BN, int BK, int TM, int TN, bool RESID>
__global__ void sgemm_kernel(const float* __restrict__ A,
                             const float* __restrict__ B,
                             const float* __restrict__ R,
                             float* __restrict__ C,
                             int M, int N, int K) {
    constexpr int THREADS = (BM / TM) * (BN / TN);
    static_assert(TM % 4 == 0 && TN % 4 == 0, "");
    __shared__ float As[BK][BM];
    __shared__ float Bs[BK][BN];

    const int tid = threadIdx.x;
    const int bm = blockIdx.y * BM;
    const int bn = blockIdx.x * BN;

    constexpr int K4 = BK / 4;
    constexpr int N4 = BN / 4;
    constexpr int A_PER = (BM * BK / 4) / THREADS;
    constexpr int B_PER = (BK * BN / 4) / THREADS;

    const int ty = tid / (BN / TN);
    const int tx = tid % (BN / TN);

    float acc[TM][TN];
    #pragma unroll
    for (int i = 0; i < TM; i++)
        #pragma unroll
        for (int j = 0; j < TN; j++) acc[i][j] = 0.f;

    for (int k0 = 0; k0 < K; k0 += BK) {
        #pragma unroll
        for (int l = 0; l < A_PER; l++) {
            int idx = tid + l * THREADS;
            int row = idx / K4;
            int kk  = (idx % K4) * 4;
            float4 v = *reinterpret_cast<const float4*>(&A[(size_t)(bm + row) * K + k0 + kk]);
            As[kk + 0][row] = v.x;  As[kk + 1][row] = v.y;
            As[kk + 2][row] = v.z;  As[kk + 3][row] = v.w;
        }
        #pragma unroll
        for (int l = 0; l < B_PER; l++) {
            int idx = tid + l * THREADS;
            int row = idx / N4;
            int cc  = (idx % N4) * 4;
            int gcol = bn + cc;
            float4 v = make_float4(0.f, 0.f, 0.f, 0.f);
            if (gcol < N)
                v = *reinterpret_cast<const float4*>(&B[(size_t)(k0 + row) * N + gcol]);
            *reinterpret_cast<float4*>(&Bs[row][cc]) = v;
        }
        __syncthreads();

        #pragma unroll
        for (int kk = 0; kk < BK; kk++) {
            float ra[TM], rb[TN];
            #pragma unroll
            for (int i = 0; i < TM / 4; i++)
                *reinterpret_cast<float4*>(&ra[i * 4]) =
                    *reinterpret_cast<const float4*>(&As[kk][ty * TM + i * 4]);
            #pragma unroll
            for (int j = 0; j < TN / 4; j++)
                *reinterpret_cast<float4*>(&rb[j * 4]) =
                    *reinterpret_cast<const float4*>(&Bs[kk][tx * TN + j * 4]);
            #pragma unroll
            for (int i = 0; i < TM; i++)
                #pragma unroll
                for (int j = 0; j < TN; j++)
                    acc[i][j] += ra[i] * rb[j];
        }
        __syncthreads();
    }

    #pragma unroll
    for (int i = 0; i < TM; i++) {
        int row = bm + ty * TM + i;
        #pragma unroll
        for (int j = 0; j < TN; j++) {
            int col = bn + tx * TN + j;
            if (col < N) {
                float v = acc[i][j];
                if (RESID) v += R[(size_t)row * N + col];
                C[(size_t)row * N + col] = v;
            }
        }
    }
}

// ---------------- causal depthwise conv (4 taps) + SiLU ----------------
__global__ void conv_silu_kernel(const float* __restrict__ proj,
                                 const float* __restrict__ w,     // [4][D_INNER]
                                 const float* __restrict__ bias,  // [D_INNER]
                                 float* __restrict__ h) {
    int i = blockIdx.x * blockDim.x + threadIdx.x;   // SEQ*D_INNER
    int t = i >> 11;            // /2048
    int c = i & (D_INNER - 1);
    float acc = bias[c];
    #pragma unroll
    for (int k = 0; k < D_CONV; k++) {
        int s = t + k - (D_CONV - 1);
        if (s >= 0)
            acc += w[k * D_INNER + c] * proj[(size_t)s * PROJ + COL_SSM + c];
    }
    h[i] = siluf(acc);
}

// ---------------- dt = softplus(dt_raw + bias), la = cumsum(A*dt) ----------------
__global__ void dt_scan_kernel(const float* __restrict__ proj,
                               const float* __restrict__ dt_bias,
                               const float* __restrict__ A_log,
                               float* __restrict__ dt_out,
                               float* __restrict__ la_out) {
    int h = blockIdx.x;      // head
    int t = threadIdx.x;     // 512 threads
    float z = proj[(size_t)t * PROJ + COL_DT + h] + dt_bias[h];
    float dt = (z > 20.f) ? z : log1pf(expf(z));
    dt_out[h * SEQ + t] = dt;
    float A = -expf(A_log[h]);

    __shared__ float buf[2][SEQ];
    buf[0][t] = A * dt;
    __syncthreads();
    int src = 0;
    #pragma unroll
    for (int off = 1; off < SEQ; off <<= 1) {
        float v = buf[src][t];
        if (t >= off) v += buf[src][t - off];
        buf[1 - src][t] = v;
        __syncthreads();
        src ^= 1;
    }
    la_out[h * SEQ + t] = buf[src][t];
}

// ---------------- G = C @ B^T (512x512, K=64) ----------------
__global__ void cbt_kernel(const float* __restrict__ proj,
                           float* __restrict__ G) {
    __shared__ float Csh[D_STATE][64 + 1];   // [n][t]
    __shared__ float Bsh[D_STATE][64 + 1];   // [n][s]
    int tid = threadIdx.x;                   // 256
    int t0 = blockIdx.y * 64;
    int s0 = blockIdx.x * 64;

    #pragma unroll
    for (int l = 0; l < 16; l++) {
        int idx = tid + l * 256;
        int r = idx >> 6;         // row within tile
        int n = idx & 63;
        Csh[n][r] = proj[(size_t)(t0 + r) * PROJ + COL_C + n];
        Bsh[n][r] = proj[(size_t)(s0 + r) * PROJ + COL_B + n];
    }
    __syncthreads();

    int ty = tid / 16, tx = tid % 16;
    int r0 = ty * 4, c0 = tx * 4;
    float acc[4][4];
    #pragma unroll
    for (int i = 0; i < 4; i++)
        #pragma unroll
        for (int j = 0; j < 4; j++) acc[i][j] = 0.f;

    #pragma unroll
    for (int k = 0; k < D_STATE; k++) {
        float ra[4], rb[4];
        #pragma unroll
        for (int i = 0; i < 4; i++) ra[i] = Csh[k][r0 + i];
        #pragma unroll
        for (int j = 0; j < 4; j++) rb[j] = Bsh[k][c0 + j];
        #pragma unroll
        for (int i = 0; i < 4; i++)
            #pragma unroll
            for (int j = 0; j < 4; j++) acc[i][j] += ra[i] * rb[j];
    }
    #pragma unroll
    for (int i = 0; i < 4; i++)
        #pragma unroll
        for (int j = 0; j < 4; j++)
            G[(size_t)(t0 + r0 + i) * SEQ + s0 + c0 + j] = acc[i][j];
}

// ---------------- SSM as decay-masked attention ----------------
// y[t,h,p] = sum_{s<=t} exp(la[t]-la[s]) * dt[s] * G[t,s] * hconv[s, h*64+p]
__global__ void attn_kernel(const float* __restrict__ G,
                            const float* __restrict__ hconv,
                            const float* __restrict__ la,
                            const float* __restrict__ dt,
                            float* __restrict__ y) {
    int t0 = blockIdx.x * 64;
    int h  = blockIdx.y;
    int tid = threadIdx.x;   // 256

    __shared__ float Wt[64][64 + 1];   // W^T : [s][t]
    __shared__ float Xs[64][64 + 1];   // [s][p]
    __shared__ float la_t[64], la_s[64], dt_s[64];

    if (tid < 64) la_t[tid] = la[h * SEQ + t0 + tid];

    int ty = tid / 16, tx = tid % 16;
    int r0 = ty * 4, c0 = tx * 4;
    float acc[4][4];
    #pragma unroll
    for (int i = 0; i < 4; i++)
        #pragma unroll
        for (int j = 0; j < 4; j++) acc[i][j] = 0.f;

    int nst = blockIdx.x + 1;   // s-tiles 0..ti
    for (int si = 0; si < nst; si++) {
        int s0 = si * 64;
        __syncthreads();   // protect Xs/la_s/Wt from previous iteration readers
        if (tid < 64) {
            la_s[tid] = la[h * SEQ + s0 + tid];
            dt_s[tid] = dt[h * SEQ + s0 + tid];
        }
        #pragma unroll
        for (int l = 0; l < 16; l++) {
            int idx = tid + l * 256;
            int sl = idx >> 6, p = idx & 63;
            Xs[sl][p] = hconv[(size_t)(s0 + sl) * D_INNER + h * HEAD_DIM + p];
        }
        __syncthreads();
        // build W^T tile: coalesced G reads (row t, consecutive s)
        #pragma unroll
        for (int l = 0; l < 16; l++) {
            int idx = tid + l * 256;
            int tl = idx >> 6, sl = idx & 63;
            float w = 0.f;
            if (s0 + sl <= t0 + tl) {
                float g = G[(size_t)(t0 + tl) * SEQ + s0 + sl];
                w = g * expf(la_t[tl] - la_s[sl]) * dt_s[sl];
            }
            Wt[sl][tl] = w;
        }
        __syncthreads();
        #pragma unroll
        for (int k = 0; k < 64; k++) {
            float ra[4], rb[4];
            #pragma unroll
            for (int i = 0; i < 4; i++) ra[i] = Wt[k][r0 + i];
            #pragma unroll
            for (int j = 0; j < 4; j++) rb[j] = Xs[k][c0 + j];
            #pragma unroll
            for (int i = 0; i < 4; i++)
                #pragma unroll
                for (int j = 0; j < 4; j++) acc[i][j] += ra[i] * rb[j];
        }
    }

    #pragma unroll
    for (int i = 0; i < 4; i++)
        #pragma unroll
        for (int j = 0; j < 4; j++)
            y[(size_t)(t0 + r0 + i) * D_INNER + h * HEAD_DIM + c0 + j] = acc[i][j];
}

// ---------------- gate: y *= silu(gate) ----------------
__global__ void gate_kernel(const float* __restrict__ proj,
                            float* __restrict__ y) {
    int i = blockIdx.x * blockDim.x + threadIdx.x;   // SEQ*D_INNER
    int t = i >> 11;
    int c = i & (D_INNER - 1);
    float g = proj[(size_t)t * PROJ + COL_GATE + c];
    y[i] *= siluf(g);
}

// ---------------- host launch ----------------
extern "C" void kernel_launch(void* const* d_in, const int* in_sizes, int n_in,
                              void* d_out, int out_size) {
    const float* x        = (const float*)d_in[0];
    const float* nscale   = (const float*)d_in[1];
    const float* w_in     = (const float*)d_in[2];
    const float* conv_w   = (const float*)d_in[3];
    const float* conv_b   = (const float*)d_in[4];
    const float* A_log    = (const float*)d_in[5];
    const float* dt_bias  = (const float*)d_in[6];
    const float* w_out    = (const float*)d_in[7];
    float* out = (float*)d_out;

    void *p_xn, *p_proj, *p_h, *p_dt, *p_la, *p_G, *p_y;
    cudaGetSymbolAddress(&p_xn,  g_xn);
    cudaGetSymbolAddress(&p_proj, g_proj);
    cudaGetSymbolAddress(&p_h,   g_h);
    cudaGetSymbolAddress(&p_dt,  g_dt);
    cudaGetSymbolAddress(&p_la,  g_la);
    cudaGetSymbolAddress(&p_G,   g_G);
    cudaGetSymbolAddress(&p_y,   g_y);
    float* xn   = (float*)p_xn;
    float* proj = (float*)p_proj;
    float* hbuf = (float*)p_h;
    float* dt   = (float*)p_dt;
    float* la   = (float*)p_la;
    float* G    = (float*)p_G;
    float* y    = (float*)p_y;

    rmsnorm_kernel<<<SEQ, 256>>>(x, nscale, xn);

    // GEMM1: 512 x 4256 x 1024
    {
        dim3 grid((PROJ + 127) / 128, SEQ / 128);
        sgemm_kernel<128, 128, 8, 8, 8, false><<<grid, 256>>>(
            xn, w_in, nullptr, proj, SEQ, PROJ, N_EMBD);
    }

    conv_silu_kernel<<<(SEQ * D_INNER) / 256, 256>>>(proj, conv_w, conv_b, hbuf);
    dt_scan_kernel<<<N_HEADS, SEQ>>>(proj, dt_bias, A_log, dt, la);
    cbt_kernel<<<dim3(SEQ / 64, SEQ / 64), 256>>>(proj, G);
    attn_kernel<<<dim3(SEQ / 64, N_HEADS), 256>>>(G, hbuf, la, dt, y);
    gate_kernel<<<(SEQ * D_INNER) / 256, 256>>>(proj, y);

    // GEMM2: 512 x 1024 x 2048 + residual
    {
        dim3 grid(N_EMBD / 64, SEQ / 64);
        sgemm_kernel<64, 64, 16, 4, 4, true><<<grid, 256>>>(
            y, w_out, x, out, SEQ, N_EMBD, D_INNER);
    }
}

// round 3
// speedup vs baseline: 1.4359x; 1.4359x over previous
#include <cuda_runtime.h>
#include <cuda_bf16.h>
#include <mma.h>
#include <cstdint>
#include <math.h>

using namespace nvcuda;

// ---------------- problem constants ----------------
#define N_EMBD   1024
#define D_INNER  2048
#define D_STATE  64
#define N_HEADS  32
#define HEAD_DIM 64
#define D_CONV   4
#define SEQ      512
#define PROJ     4256          // 2*D_INNER + N_HEADS + 2*D_STATE
#define COL_GATE 0
#define COL_SSM  2048
#define COL_DT   4096
#define COL_B    4128
#define COL_C    4192

// ---------------- scratch (no allocation allowed) ----------------
__device__ float g_xn  [SEQ * N_EMBD];
__device__ float g_proj[SEQ * PROJ];
__device__ float g_h   [SEQ * D_INNER];
__device__ float g_dt  [N_HEADS * SEQ];   // [h][t]
__device__ float g_la  [N_HEADS * SEQ];   // [h][t] inclusive cumsum of A*dt
__device__ float g_G   [SEQ * SEQ];       // C @ B^T
__device__ float g_y   [SEQ * D_INNER];
__device__ float g_wT1 [PROJ * N_EMBD];   // w_in^T  [4256][1024]
__device__ float g_wT2 [N_EMBD * D_INNER];// w_out^T [1024][2048]

__device__ __forceinline__ float siluf(float v) {
    return v / (1.0f + expf(-v));
}

__device__ __forceinline__ uint32_t smem_u32(const void* p) {
    uint32_t a;
    asm("{ .reg .u64 tmp; cvta.to.shared.u64 tmp, %1; cvt.u32.u64 %0, tmp; }"
        : "=r"(a) : "l"(p));
    return a;
}
__device__ __forceinline__ void cp_async16(uint32_t dst, const void* src) {
    asm volatile("cp.async.cg.shared.global [%0], [%1], 16;\n"
                 :: "r"(dst), "l"(src) : "memory");
}
__device__ __forceinline__ void cp_commit() {
    asm volatile("cp.async.commit_group;\n" ::: "memory");
}
template<int NN> __device__ __forceinline__ void cp_wait() {
    asm volatile("cp.async.wait_group %0;\n" :: "n"(NN) : "memory");
}

// ================= tf32 WMMA GEMM =================
// C[M,N] = A[M,K] @ BT[N,K]^T (+ optional residual R).
// Row-major A/C/R; BT is [N][K] (K-major), consumed as col_major fragments.
// M % BM == 0, K % 16 == 0, N % 16 == 0 (edge tiles guarded at frag level).
template<int BM, int BN, int WARPS_M, int WARPS_N, bool RESID>
__global__ void __launch_bounds__(WARPS_M * WARPS_N * 32)
wmma_gemm_kernel(const float* __restrict__ A,
                 const float* __restrict__ BT,
                 const float* __restrict__ R,
                 float* __restrict__ C,
                 int M, int N, int K)
{
    constexpr int THREADS = WARPS_M * WARPS_N * 32;
    constexpr int BK  = 16;
    constexpr int LD  = BK + 4;          // 20 floats (80B, 16B-aligned rows)
    constexpr int WM  = BM / WARPS_M;    // warp tile m
    constexpr int WN  = BN / WARPS_N;    // warp tile n
    constexpr int MF  = WM / 16;
    constexpr int NF  = WN / 16;
    constexpr int A_PER = (BM * 4) / THREADS;   // float4 loads per thread
    constexpr int B_PER = (BN * 4) / THREADS;

    __shared__ float As[2][BM][LD];
    __shared__ float Bs[2][BN][LD];

    const int tid = threadIdx.x;
    const int wid = tid >> 5;
    const int wy  = wid / WARPS_N;
    const int wx  = wid % WARPS_N;
    const int bm  = blockIdx.y * BM;
    const int bn  = blockIdx.x * BN;

    wmma::fragment<wmma::accumulator, 16, 16, 8, float> acc[MF][NF];
    #pragma unroll
    for (int i = 0; i < MF; i++)
        #pragma unroll
        for (int j = 0; j < NF; j++)
            wmma::fill_fragment(acc[i][j], 0.0f);

    auto load_stage = [&](int i, int s) {
        int k0 = i * BK;
        uint32_t zero = 0;
        #pragma unroll
        for (int l = 0; l < A_PER; l++) {
            int idx = tid + l * THREADS;
            int row = idx >> 2;
            int c4  = (idx & 3) * 4;
            cp_async16(smem_u32(&As[s][row][c4]),
                       A + (size_t)(bm + row) * K + k0 + c4);
        }
        #pragma unroll
        for (int l = 0; l < B_PER; l++) {
            int idx = tid + l * THREADS;
            int row = idx >> 2;
            int c4  = (idx & 3) * 4;
            int n   = bn + row;
            if (n < N)
                cp_async16(smem_u32(&Bs[s][row][c4]),
                           BT + (size_t)n * K + k0 + c4);
            else
                asm volatile("st.shared.v4.b32 [%0], {%1,%1,%1,%1};"
                             :: "r"(smem_u32(&Bs[s][row][c4])), "r"(zero)
                             : "memory");
        }
        cp_commit();
    };

    const int NC = K / BK;
    load_stage(0, 0);

    for (int i = 0; i < NC; i++) {
        int s = i & 1;
        if (i + 1 < NC) {
            load_stage(i + 1, s ^ 1);
            cp_wait<1>();
        } else {
            cp_wait<0>();
        }
        __syncthreads();

        #pragma unroll
        for (int kk = 0; kk < BK; kk += 8) {
            wmma::fragment<wmma::matrix_a, 16, 16, 8,
                           wmma::precision::tf32, wmma::row_major> af[MF];
            wmma::fragment<wmma::matrix_b, 16, 16, 8,
                           wmma::precision::tf32, wmma::col_major> bf[NF];
            #pragma unroll
            for (int m = 0; m < MF; m++) {
                wmma::load_matrix_sync(af[m], &As[s][wy * WM + m * 16][kk], LD);
                #pragma unroll
                for (int e = 0; e < af[m].num_elements; e++)
                    af[m].x[e] = wmma::__float_to_tf32(af[m].x[e]);
            }
            #pragma unroll
            for (int n = 0; n < NF; n++) {
                wmma::load_matrix_sync(bf[n], &Bs[s][wx * WN + n * 16][kk], LD);
                #pragma unroll
                for (int e = 0; e < bf[n].num_elements; e++)
                    bf[n].x[e] = wmma::__float_to_tf32(bf[n].x[e]);
            }
            #pragma unroll
            for (int m = 0; m < MF; m++)
                #pragma unroll
                for (int n = 0; n < NF; n++)
                    wmma::mma_sync(acc[m][n], af[m], bf[n], acc[m][n]);
        }
        __syncthreads();
    }

    // epilogue
    #pragma unroll
    for (int m = 0; m < MF; m++) {
        int row0 = bm + wy * WM + m * 16;
        #pragma unroll
        for (int n = 0; n < NF; n++) {
            int col0 = bn + wx * WN + n * 16;
            if (col0 < N) {
                if (RESID) {
                    wmma::fragment<wmma::accumulator, 16, 16, 8, float> rf;
                    wmma::load_matrix_sync(rf, &R[(size_t)row0 * N + col0],
                                           N, wmma::mem_row_major);
                    #pragma unroll
                    for (int e = 0; e < rf.num_elements; e++)
                        acc[m][n].x[e] += rf.x[e];
                }
                wmma::store_matrix_sync(&C[(size_t)row0 * N + col0],
                                        acc[m][n], N, wmma::mem_row_major);
            }
        }
    }
}

// ---------------- transpose: in[R][C] -> out[C][R] ----------------
__global__ void transpose_kernel(const float* __restrict__ in,
                                 float* __restrict__ out,
                                 int Rr, int Cc) {
    __shared__ float t[32][33];
    int c0 = blockIdx.x * 32, r0 = blockIdx.y * 32;
    int x = threadIdx.x, y = threadIdx.y;   // 32 x 8
    #pragma unroll
    for (int dy = 0; dy < 32; dy += 8)
        t[y + dy][x] = in[(size_t)(r0 + y + dy) * Cc + c0 + x];
    __syncthreads();
    #pragma unroll
    for (int dy = 0; dy < 32; dy += 8)
        out[(size_t)(c0 + y + dy) * Rr + r0 + x] = t[x][y + dy];
}

// ---------------- RMSNorm ----------------
__global__ void rmsnorm_kernel(const float* __restrict__ x,
                               const float* __restrict__ scale,
                               float* __restrict__ out) {
    int row = blockIdx.x;
    int tid = threadIdx.x;              // 256 threads, 1 float4 each
    const float4* xr = reinterpret_cast<const float4*>(x + row * N_EMBD);
    float4 v = xr[tid];
    float ss = v.x * v.x + v.y * v.y + v.z * v.z + v.w * v.w;
    #pragma unroll
    for (int o = 16; o; o >>= 1) ss += __shfl_xor_sync(0xffffffffu, ss, o);
    __shared__ float wsum[8];
    int lane = tid & 31, wid = tid >> 5;
    if (lane == 0) wsum[wid] = ss;
    __syncthreads();
    __shared__ float s_inv;
    if (tid == 0) {
        float tot = 0.f;
        #pragma unroll
        for (int i = 0; i < 8; i++) tot += wsum[i];
        s_inv = rsqrtf(tot / (float)N_EMBD + 1e-6f);
    }
    __syncthreads();
    float inv = s_inv;
    const float4 sc = reinterpret_cast<const float4*>(scale)[tid];
    float4 o;
    o.x = v.x * inv * sc.x;  o.y = v.y * inv * sc.y;
    o.z = v.z * inv * sc.z;  o.w = v.w * inv * sc.w;
    reinterpret_cast<float4*>(out + row * N_EMBD)[tid] = o;
}

// ---------------- causal depthwise conv (4 taps) + SiLU ----------------
__global__ void conv_silu_kernel(const float* __restrict__ proj,
                                 const float* __restrict__ w,
                                 const float* __restrict__ bias,
                                 float* __restrict__ h) {
    int i = blockIdx.x * blockDim.x + threadIdx.x;   // SEQ*D_INNER
    int t = i >> 11;
    int c = i & (D_INNER - 1);
    float acc = bias[c];
    #pragma unroll
    for (int k = 0; k < D_CONV; k++) {
        int s = t + k - (D_CONV - 1);
        if (s >= 0)
            acc += w[k * D_INNER + c] * proj[(size_t)s * PROJ + COL_SSM + c];
    }
    h[i] = siluf(acc);
}

// ---------------- dt = softplus(dt_raw + bias), la = cumsum(A*dt) ----------------
__global__ void dt_scan_kernel(const float* __restrict__ proj,
                               const float* __restrict__ dt_bias,
                               const float* __restrict__ A_log,
                               float* __restrict__ dt_out,
                               float* __restrict__ la_out) {
    int h = blockIdx.x;      // head
    int t = threadIdx.x;     // 512 threads
    float z = proj[(size_t)t * PROJ + COL_DT + h] + dt_bias[h];
    float dt = (z > 20.f) ? z : log1pf(expf(z));
    dt_out[h * SEQ + t] = dt;
    float A = -expf(A_log[h]);

    __shared__ float buf[2][SEQ];
    buf[0][t] = A * dt;
    __syncthreads();
    int src = 0;
    #pragma unroll
    for (int off = 1; off < SEQ; off <<= 1) {
        float v = buf[src][t];
        if (t >= off) v += buf[src][t - off];
        buf[1 - src][t] = v;
        __syncthreads();
        src ^= 1;
    }
    la_out[h * SEQ + t] = buf[src][t];
}

// ---------------- G = C @ B^T (512x512, K=64) ----------------
__global__ void cbt_kernel(const float* __restrict__ proj,
                           float* __restrict__ G) {
    __shared__ float Csh[D_STATE][64 + 1];
    __shared__ float Bsh[D_STATE][64 + 1];
    int tid = threadIdx.x;                   // 256
    int t0 = blockIdx.y * 64;
    int s0 = blockIdx.x * 64;

    #pragma unroll
    for (int l = 0; l < 16; l++) {
        int idx = tid + l * 256;
        int r = idx >> 6;
        int n = idx & 63;
        Csh[n][r] = proj[(size_t)(t0 + r) * PROJ + COL_C + n];
        Bsh[n][r] = proj[(size_t)(s0 + r) * PROJ + COL_B + n];
    }
    __syncthreads();

    int ty = tid / 16, tx = tid % 16;
    int r0 = ty * 4, c0 = tx * 4;
    float acc[4][4];
    #pragma unroll
    for (int i = 0; i < 4; i++)
        #pragma unroll
        for (int j = 0; j < 4; j++) acc[i][j] = 0.f;

    #pragma unroll
    for (int k = 0; k < D_STATE; k++) {
        float ra[4], rb[4];
        #pragma unroll
        for (int i = 0; i < 4; i++) ra[i] = Csh[k][r0 + i];
        #pragma unroll
        for (int j = 0; j < 4; j++) rb[j] = Bsh[k][c0 + j];
        #pragma unroll
        for (int i = 0; i < 4; i++)
            #pragma unroll
            for (int j = 0; j < 4; j++) acc[i][j] += ra[i] * rb[j];
    }
    #pragma unroll
    for (int i = 0; i < 4; i++)
        #pragma unroll
        for (int j = 0; j < 4; j++)
            G[(size_t)(t0 + r0 + i) * SEQ + s0 + c0 + j] = acc[i][j];
}

// ---------------- SSM as decay-masked attention ----------------
// y[t,h,p] = sum_{s<=t} exp(la[t]-la[s]) * dt[s] * G[t,s] * hconv[s, h*64+p]
__global__ void attn_kernel(const float* __restrict__ G,
                            const float* __restrict__ hconv,
                            const float* __restrict__ la,
                            const float* __restrict__ dt,
                            float* __restrict__ y) {
    int t0 = blockIdx.x * 64;
    int h  = blockIdx.y;
    int tid = threadIdx.x;   // 256

    __shared__ float Wt[64][64 + 1];
    __shared__ float Xs[64][64 + 1];
    __shared__ float la_t[64], la_s[64], dt_s[64];

    if (tid < 64) la_t[tid] = la[h * SEQ + t0 + tid];

    int ty = tid / 16, tx = tid % 16;
    int r0 = ty * 4, c0 = tx * 4;
    float acc[4][4];
    #pragma unroll
    for (int i = 0; i < 4; i++)
        #pragma unroll
        for (int j = 0; j < 4; j++) acc[i][j] = 0.f;

    int nst = blockIdx.x + 1;
    for (int si = 0; si < nst; si++) {
        int s0 = si * 64;
        __syncthreads();
        if (tid < 64) {
            la_s[tid] = la[h * SEQ + s0 + tid];
            dt_s[tid] = dt[h * SEQ + s0 + tid];
        }
        #pragma unroll
        for (int l = 0; l < 16; l++) {
            int idx = tid + l * 256;
            int sl = idx >> 6, p = idx & 63;
            Xs[sl][p] = hconv[(size_t)(s0 + sl) * D_INNER + h * HEAD_DIM + p];
        }
        __syncthreads();
        #pragma unroll
        for (int l = 0; l < 16; l++) {
            int idx = tid + l * 256;
            int tl = idx >> 6, sl = idx & 63;
            float w = 0.f;
            if (s0 + sl <= t0 + tl) {
                float g = G[(size_t)(t0 + tl) * SEQ + s0 + sl];
                w = g * expf(la_t[tl] - la_s[sl]) * dt_s[sl];
            }
            Wt[sl][tl] = w;
        }
        __syncthreads();
        #pragma unroll
        for (int k = 0; k < 64; k++) {
            float ra[4], rb[4];
            #pragma unroll
            for (int i = 0; i < 4; i++) ra[i] = Wt[k][r0 + i];
            #pragma unroll
            for (int j = 0; j < 4; j++) rb[j] = Xs[k][c0 + j];
            #pragma unroll
            for (int i = 0; i < 4; i++)
                #pragma unroll
                for (int j = 0; j < 4; j++) acc[i][j] += ra[i] * rb[j];
        }
    }

    #pragma unroll
    for (int i = 0; i < 4; i++)
        #pragma unroll
        for (int j = 0; j < 4; j++)
            y[(size_t)(t0 + r0 + i) * D_INNER + h * HEAD_DIM + c0 + j] = acc[i][j];
}

// ---------------- gate: y *= silu(gate) ----------------
__global__ void gate_kernel(const float* __restrict__ proj,
                            float* __restrict__ y) {
    int i = blockIdx.x * blockDim.x + threadIdx.x;   // SEQ*D_INNER
    int t = i >> 11;
    int c = i & (D_INNER - 1);
    float g = proj[(size_t)t * PROJ + COL_GATE + c];
    y[i] *= siluf(g);
}

// ---------------- host launch ----------------
extern "C" void kernel_launch(void* const* d_in, const int* in_sizes, int n_in,
                              void* d_out, int out_size) {
    const float* x        = (const float*)d_in[0];
    const float* nscale   = (const float*)d_in[1];
    const float* w_in     = (const float*)d_in[2];
    const float* conv_w   = (const float*)d_in[3];
    const float* conv_b   = (const float*)d_in[4];
    const float* A_log    = (const float*)d_in[5];
    const float* dt_bias  = (const float*)d_in[6];
    const float* w_out    = (const float*)d_in[7];
    float* out = (float*)d_out;

    void *p_xn, *p_proj, *p_h, *p_dt, *p_la, *p_G, *p_y, *p_w1, *p_w2;
    cudaGetSymbolAddress(&p_xn,  g_xn);
    cudaGetSymbolAddress(&p_proj, g_proj);
    cudaGetSymbolAddress(&p_h,   g_h);
    cudaGetSymbolAddress(&p_dt,  g_dt);
    cudaGetSymbolAddress(&p_la,  g_la);
    cudaGetSymbolAddress(&p_G,   g_G);
    cudaGetSymbolAddress(&p_y,   g_y);
    cudaGetSymbolAddress(&p_w1,  g_wT1);
    cudaGetSymbolAddress(&p_w2,  g_wT2);
    float* xn   = (float*)p_xn;
    float* proj = (float*)p_proj;
    float* hbuf = (float*)p_h;
    float* dt   = (float*)p_dt;
    float* la   = (float*)p_la;
    float* G    = (float*)p_G;
    float* y    = (float*)p_y;
    float* wT1  = (float*)p_w1;
    float* wT2  = (float*)p_w2;

    // weight transposes (K-major operands for mma B)
    transpose_kernel<<<dim3(PROJ / 32, N_EMBD / 32), dim3(32, 8)>>>(
        w_in, wT1, N_EMBD, PROJ);
    transpose_kernel<<<dim3(N_EMBD / 32, D_INNER / 32), dim3(32, 8)>>>(
        w_out, wT2, D_INNER, N_EMBD);

    rmsnorm_kernel<<<SEQ, 256>>>(x, nscale, xn);

    // GEMM1: proj[512,4256] = xn[512,1024] @ w_in   (tf32 tensor cores)
    {
        dim3 grid((PROJ + 127) / 128, SEQ / 128);   // 34 x 4
        wmma_gemm_kernel<128, 128, 4, 2, false><<<grid, 256>>>(
            xn, wT1, nullptr, proj, SEQ, PROJ, N_EMBD);
    }

    conv_silu_kernel<<<(SEQ * D_INNER) / 256, 256>>>(proj, conv_w, conv_b, hbuf);
    dt_scan_kernel<<<N_HEADS, SEQ>>>(proj, dt_bias, A_log, dt, la);
    cbt_kernel<<<dim3(SEQ / 64, SEQ / 64), 256>>>(proj, G);
    attn_kernel<<<dim3(SEQ / 64, N_HEADS), 256>>>(G, hbuf, la, dt, y);
    gate_kernel<<<(SEQ * D_INNER) / 256, 256>>>(proj, y);

    // GEMM2: out[512,1024] = y[512,2048] @ w_out + x   (tf32 tensor cores)
    {
        dim3 grid(N_EMBD / 64, SEQ / 64);            // 16 x 8
        wmma_gemm_kernel<64, 64, 2, 2, true><<<grid, 128>>>(
            y, wT2, x, out, SEQ, N_EMBD, D_INNER);
    }
}

// round 4
// speedup vs baseline: 2.2755x; 1.5847x over previous
#include <cuda_runtime.h>
#include <cuda_bf16.h>
#include <mma.h>
#include <cstdint>
#include <math.h>

using namespace nvcuda;

// ---------------- problem constants ----------------
#define N_EMBD   1024
#define D_INNER  2048
#define D_STATE  64
#define N_HEADS  32
#define HEAD_DIM 64
#define D_CONV   4
#define SEQ      512
#define PROJ     4256          // 2*D_INNER + N_HEADS + 2*D_STATE
#define COL_GATE 0
#define COL_SSM  2048
#define COL_DT   4096
#define COL_B    4128
#define COL_C    4192

// ---------------- scratch (no allocation allowed) ----------------
__device__ __nv_bfloat16 g_xnb [SEQ * N_EMBD];    // bf16 rmsnorm output
__device__ float         g_proj[SEQ * PROJ];
__device__ __nv_bfloat16 g_hb  [SEQ * D_INNER];   // bf16 conv+silu output
__device__ float         g_dt  [N_HEADS * SEQ];   // [h][t]
__device__ float         g_la  [N_HEADS * SEQ];   // [h][t] cumsum A*dt
__device__ float         g_G   [SEQ * SEQ];       // C @ B^T
__device__ float         g_y   [SEQ * D_INNER];   // attn output fp32
__device__ __nv_bfloat16 g_yb  [SEQ * D_INNER];   // gated y, bf16
__device__ __nv_bfloat16 g_wT1b[PROJ * N_EMBD];   // w_in^T  bf16
__device__ __nv_bfloat16 g_wT2b[N_EMBD * D_INNER];// w_out^T bf16

__device__ __forceinline__ float siluf(float v) {
    return v / (1.0f + expf(-v));
}

__device__ __forceinline__ uint32_t smem_u32(const void* p) {
    uint32_t a;
    asm("{ .reg .u64 tmp; cvta.to.shared.u64 tmp, %1; cvt.u32.u64 %0, tmp; }"
        : "=r"(a) : "l"(p));
    return a;
}
__device__ __forceinline__ void cp_async16(uint32_t dst, const void* src) {
    asm volatile("cp.async.cg.shared.global [%0], [%1], 16;\n"
                 :: "r"(dst), "l"(src) : "memory");
}
__device__ __forceinline__ void cp_commit() {
    asm volatile("cp.async.commit_group;\n" ::: "memory");
}
template<int NN> __device__ __forceinline__ void cp_wait() {
    asm volatile("cp.async.wait_group %0;\n" :: "n"(NN) : "memory");
}

// ================= bf16 WMMA GEMM =================
// C[M,N] = A[M,K] @ BT[N,K]^T (+ optional fp32 residual R).
// A bf16 row-major; BT bf16 [N][K] (K-major), consumed as col_major frags.
// M % BM == 0, K % 32 == 0, N % 16 == 0.
template<int BM, int BN, int WARPS_M, int WARPS_N, bool RESID>
__global__ void __launch_bounds__(WARPS_M * WARPS_N * 32)
bf16_gemm_kernel(const __nv_bfloat16* __restrict__ A,
                 const __nv_bfloat16* __restrict__ BT,
                 const float* __restrict__ R,
                 float* __restrict__ C,
                 int M, int N, int K)
{
    constexpr int THREADS = WARPS_M * WARPS_N * 32;
    constexpr int BK  = 32;
    constexpr int LD  = BK + 8;          // 40 halves = 80B rows (16B aligned)
    constexpr int WM  = BM / WARPS_M;
    constexpr int WN  = BN / WARPS_N;
    constexpr int MF  = WM / 16;
    constexpr int NF  = WN / 16;
    constexpr int CH  = BK / 8;          // 16B chunks per row = 4
    constexpr int A_PER = (BM * CH) / THREADS;
    constexpr int B_PER = (BN * CH) / THREADS;

    __shared__ __nv_bfloat16 As[2][BM][LD];
    __shared__ __nv_bfloat16 Bs[2][BN][LD];

    const int tid = threadIdx.x;
    const int wid = tid >> 5;
    const int wy  = wid / WARPS_N;
    const int wx  = wid % WARPS_N;
    const int bm  = blockIdx.y * BM;
    const int bn  = blockIdx.x * BN;

    wmma::fragment<wmma::accumulator, 16, 16, 16, float> acc[MF][NF];
    #pragma unroll
    for (int i = 0; i < MF; i++)
        #pragma unroll
        for (int j = 0; j < NF; j++)
            wmma::fill_fragment(acc[i][j], 0.0f);

    auto load_stage = [&](int i, int s) {
        int k0 = i * BK;
        uint32_t zero = 0;
        #pragma unroll
        for (int l = 0; l < A_PER; l++) {
            int idx = tid + l * THREADS;
            int row = idx / CH;
            int c8  = (idx % CH) * 8;
            cp_async16(smem_u32(&As[s][row][c8]),
                       A + (size_t)(bm + row) * K + k0 + c8);
        }
        #pragma unroll
        for (int l = 0; l < B_PER; l++) {
            int idx = tid + l * THREADS;
            int row = idx / CH;
            int c8  = (idx % CH) * 8;
            int n   = bn + row;
            if (n < N)
                cp_async16(smem_u32(&Bs[s][row][c8]),
                           BT + (size_t)n * K + k0 + c8);
            else
                asm volatile("st.shared.v4.b32 [%0], {%1,%1,%1,%1};"
                             :: "r"(smem_u32(&Bs[s][row][c8])), "r"(zero)
                             : "memory");
        }
        cp_commit();
    };

    const int NC = K / BK;
    load_stage(0, 0);

    for (int i = 0; i < NC; i++) {
        int s = i & 1;
        if (i + 1 < NC) {
            load_stage(i + 1, s ^ 1);
            cp_wait<1>();
        } else {
            cp_wait<0>();
        }
        __syncthreads();

        #pragma unroll
        for (int kk = 0; kk < BK; kk += 16) {
            wmma::fragment<wmma::matrix_a, 16, 16, 16,
                           __nv_bfloat16, wmma::row_major> af[MF];
            wmma::fragment<wmma::matrix_b, 16, 16, 16,
                           __nv_bfloat16, wmma::col_major> bf[NF];
            #pragma unroll
            for (int m = 0; m < MF; m++)
                wmma::load_matrix_sync(af[m], &As[s][wy * WM + m * 16][kk], LD);
            #pragma unroll
            for (int n = 0; n < NF; n++)
                wmma::load_matrix_sync(bf[n], &Bs[s][wx * WN + n * 16][kk], LD);
            #pragma unroll
            for (int m = 0; m < MF; m++)
                #pragma unroll
                for (int n = 0; n < NF; n++)
                    wmma::mma_sync(acc[m][n], af[m], bf[n], acc[m][n]);
        }
        __syncthreads();
    }

    // epilogue
    #pragma unroll
    for (int m = 0; m < MF; m++) {
        int row0 = bm + wy * WM + m * 16;
        #pragma unroll
        for (int n = 0; n < NF; n++) {
            int col0 = bn + wx * WN + n * 16;
            if (col0 < N) {
                if (RESID) {
                    wmma::fragment<wmma::accumulator, 16, 16, 16, float> rf;
                    wmma::load_matrix_sync(rf, &R[(size_t)row0 * N + col0],
                                           N, wmma::mem_row_major);
                    #pragma unroll
                    for (int e = 0; e < rf.num_elements; e++)
                        acc[m][n].x[e] += rf.x[e];
                }
                wmma::store_matrix_sync(&C[(size_t)row0 * N + col0],
                                        acc[m][n], N, wmma::mem_row_major);
            }
        }
    }
}

// ---------------- transpose + bf16: in[R][C] fp32 -> out[C][R] bf16 --------
__global__ void transpose_bf16_kernel(const float* __restrict__ in,
                                      __nv_bfloat16* __restrict__ out,
                                      int Rr, int Cc) {
    __shared__ float t[32][33];
    int c0 = blockIdx.x * 32, r0 = blockIdx.y * 32;
    int x = threadIdx.x, y = threadIdx.y;   // 32 x 8
    #pragma unroll
    for (int dy = 0; dy < 32; dy += 8)
        t[y + dy][x] = in[(size_t)(r0 + y + dy) * Cc + c0 + x];
    __syncthreads();
    #pragma unroll
    for (int dy = 0; dy < 32; dy += 8)
        out[(size_t)(c0 + y + dy) * Rr + r0 + x] =
            __float2bfloat16(t[x][y + dy]);
}

// ---------------- RMSNorm (bf16 output) ----------------
__global__ void rmsnorm_kernel(const float* __restrict__ x,
                               const float* __restrict__ scale,
                               __nv_bfloat16* __restrict__ out) {
    int row = blockIdx.x;
    int tid = threadIdx.x;              // 256 threads, 1 float4 each
    const float4* xr = reinterpret_cast<const float4*>(x + row * N_EMBD);
    float4 v = xr[tid];
    float ss = v.x * v.x + v.y * v.y + v.z * v.z + v.w * v.w;
    #pragma unroll
    for (int o = 16; o; o >>= 1) ss += __shfl_xor_sync(0xffffffffu, ss, o);
    __shared__ float wsum[8];
    int lane = tid & 31, wid = tid >> 5;
    if (lane == 0) wsum[wid] = ss;
    __syncthreads();
    __shared__ float s_inv;
    if (tid == 0) {
        float tot = 0.f;
        #pragma unroll
        for (int i = 0; i < 8; i++) tot += wsum[i];
        s_inv = rsqrtf(tot / (float)N_EMBD + 1e-6f);
    }
    __syncthreads();
    float inv = s_inv;
    const float4 sc = reinterpret_cast<const float4*>(scale)[tid];
    __nv_bfloat162 o01 = __floats2bfloat162_rn(v.x * inv * sc.x, v.y * inv * sc.y);
    __nv_bfloat162 o23 = __floats2bfloat162_rn(v.z * inv * sc.z, v.w * inv * sc.w);
    uint2 pk;
    pk.x = *reinterpret_cast<uint32_t*>(&o01);
    pk.y = *reinterpret_cast<uint32_t*>(&o23);
    *reinterpret_cast<uint2*>(out + row * N_EMBD + tid * 4) = pk;
}

// ---------------- causal depthwise conv (4 taps) + SiLU -> bf16 ------------
__global__ void conv_silu_kernel(const float* __restrict__ proj,
                                 const float* __restrict__ w,
                                 const float* __restrict__ bias,
                                 __nv_bfloat16* __restrict__ h) {
    int i = blockIdx.x * blockDim.x + threadIdx.x;   // SEQ*D_INNER
    int t = i >> 11;
    int c = i & (D_INNER - 1);
    float acc = bias[c];
    #pragma unroll
    for (int k = 0; k < D_CONV; k++) {
        int s = t + k - (D_CONV - 1);
        if (s >= 0)
            acc += w[k * D_INNER + c] * proj[(size_t)s * PROJ + COL_SSM + c];
    }
    h[i] = __float2bfloat16(siluf(acc));
}

// ---------------- dt = softplus(dt_raw + bias), la = cumsum(A*dt) ----------
__global__ void dt_scan_kernel(const float* __restrict__ proj,
                               const float* __restrict__ dt_bias,
                               const float* __restrict__ A_log,
                               float* __restrict__ dt_out,
                               float* __restrict__ la_out) {
    int h = blockIdx.x;      // head
    int t = threadIdx.x;     // 512 threads
    float z = proj[(size_t)t * PROJ + COL_DT + h] + dt_bias[h];
    float dt = (z > 20.f) ? z : log1pf(expf(z));
    dt_out[h * SEQ + t] = dt;
    float A = -expf(A_log[h]);

    __shared__ float buf[2][SEQ];
    buf[0][t] = A * dt;
    __syncthreads();
    int src = 0;
    #pragma unroll
    for (int off = 1; off < SEQ; off <<= 1) {
        float v = buf[src][t];
        if (t >= off) v += buf[src][t - off];
        buf[1 - src][t] = v;
        __syncthreads();
        src ^= 1;
    }
    la_out[h * SEQ + t] = buf[src][t];
}

// ---------------- G = C @ B^T (512x512, K=64) ----------------
__global__ void cbt_kernel(const float* __restrict__ proj,
                           float* __restrict__ G) {
    __shared__ float Csh[D_STATE][64 + 1];
    __shared__ float Bsh[D_STATE][64 + 1];
    int tid = threadIdx.x;                   // 256
    int t0 = blockIdx.y * 64;
    int s0 = blockIdx.x * 64;

    #pragma unroll
    for (int l = 0; l < 16; l++) {
        int idx = tid + l * 256;
        int r = idx >> 6;
        int n = idx & 63;
        Csh[n][r] = proj[(size_t)(t0 + r) * PROJ + COL_C + n];
        Bsh[n][r] = proj[(size_t)(s0 + r) * PROJ + COL_B + n];
    }
    __syncthreads();

    int ty = tid / 16, tx = tid % 16;
    int r0 = ty * 4, c0 = tx * 4;
    float acc[4][4];
    #pragma unroll
    for (int i = 0; i < 4; i++)
        #pragma unroll
        for (int j = 0; j < 4; j++) acc[i][j] = 0.f;

    #pragma unroll
    for (int k = 0; k < D_STATE; k++) {
        float ra[4], rb[4];
        #pragma unroll
        for (int i = 0; i < 4; i++) ra[i] = Csh[k][r0 + i];
        #pragma unroll
        for (int j = 0; j < 4; j++) rb[j] = Bsh[k][c0 + j];
        #pragma unroll
        for (int i = 0; i < 4; i++)
            #pragma unroll
            for (int j = 0; j < 4; j++) acc[i][j] += ra[i] * rb[j];
    }
    #pragma unroll
    for (int i = 0; i < 4; i++)
        #pragma unroll
        for (int j = 0; j < 4; j++)
            G[(size_t)(t0 + r0 + i) * SEQ + s0 + c0 + j] = acc[i][j];
}

// ---------------- SSM as decay-masked attention (bf16 WMMA) ----------------
// y[t,h,p] = sum_{s<=t} exp(la[t]-la[s]) * dt[s] * G[t,s] * h[s, head*64+p]
__global__ void __launch_bounds__(128)
attn_wmma_kernel(const float* __restrict__ G,
                 const __nv_bfloat16* __restrict__ hb,
                 const float* __restrict__ la,
                 const float* __restrict__ dt,
                 float* __restrict__ y) {
    const int ti   = blockIdx.x;
    const int head = blockIdx.y;
    const int t0   = ti * 64;
    const int tid  = threadIdx.x;   // 128 threads, 4 warps
    const int wid  = tid >> 5;

    __shared__ __nv_bfloat16 Ws[64][72];   // W[t][s]
    __shared__ __nv_bfloat16 Xs[64][72];   // X[s][p]
    __shared__ float la_t[64], la_s[64], dt_s[64];

    if (tid < 64) la_t[tid] = la[head * SEQ + t0 + tid];

    wmma::fragment<wmma::accumulator, 16, 16, 16, float> acc[4];
    #pragma unroll
    for (int n = 0; n < 4; n++) wmma::fill_fragment(acc[n], 0.0f);

    for (int si = 0; si <= ti; si++) {
        int s0 = si * 64;
        __syncthreads();   // protect smem from previous iteration's readers
        if (tid < 64) {
            la_s[tid] = la[head * SEQ + s0 + tid];
            dt_s[tid] = dt[head * SEQ + s0 + tid];
        }
        // X tile: 64x64 bf16, 8B vector loads
        #pragma unroll
        for (int l = 0; l < 8; l++) {
            int idx = tid + l * 128;
            int sl = idx >> 4, c = idx & 15;
            *reinterpret_cast<uint2*>(&Xs[sl][c * 4]) =
                *reinterpret_cast<const uint2*>(
                    &hb[(size_t)(s0 + sl) * D_INNER + head * HEAD_DIM + c * 4]);
        }
        __syncthreads();
        // W tile build (fp32 math, bf16 store)
        #pragma unroll
        for (int l = 0; l < 32; l++) {
            int idx = tid + l * 128;
            int tl = idx >> 6, sl = idx & 63;
            float w = 0.f;
            if (s0 + sl <= t0 + tl) {
                float g = G[(size_t)(t0 + tl) * SEQ + s0 + sl];
                w = g * expf(la_t[tl] - la_s[sl]) * dt_s[sl];
            }
            Ws[tl][sl] = __float2bfloat16(w);
        }
        __syncthreads();
        // 16x64 output strip per warp, K=64
        #pragma unroll
        for (int ks = 0; ks < 4; ks++) {
            wmma::fragment<wmma::matrix_a, 16, 16, 16,
                           __nv_bfloat16, wmma::row_major> af;
            wmma::load_matrix_sync(af, &Ws[wid * 16][ks * 16], 72);
            #pragma unroll
            for (int n = 0; n < 4; n++) {
                wmma::fragment<wmma::matrix_b, 16, 16, 16,
                               __nv_bfloat16, wmma::row_major> bf;
                wmma::load_matrix_sync(bf, &Xs[ks * 16][n * 16], 72);
                wmma::mma_sync(acc[n], af, bf, acc[n]);
            }
        }
    }

    int row0 = t0 + wid * 16;
    #pragma unroll
    for (int n = 0; n < 4; n++)
        wmma::store_matrix_sync(
            &y[(size_t)row0 * D_INNER + head * HEAD_DIM + n * 16],
            acc[n], D_INNER, wmma::mem_row_major);
}

// ---------------- gate: yb = bf16(y * silu(gate)) ----------------
__global__ void gate_kernel(const float* __restrict__ proj,
                            const float* __restrict__ y,
                            __nv_bfloat16* __restrict__ yb) {
    int i = blockIdx.x * blockDim.x + threadIdx.x;   // SEQ*D_INNER
    int t = i >> 11;
    int c = i & (D_INNER - 1);
    float g = proj[(size_t)t * PROJ + COL_GATE + c];
    yb[i] = __float2bfloat16(y[i] * siluf(g));
}

// ---------------- host launch ----------------
extern "C" void kernel_launch(void* const* d_in, const int* in_sizes, int n_in,
                              void* d_out, int out_size) {
    const float* x        = (const float*)d_in[0];
    const float* nscale   = (const float*)d_in[1];
    const float* w_in     = (const float*)d_in[2];
    const float* conv_w   = (const float*)d_in[3];
    const float* conv_b   = (const float*)d_in[4];
    const float* A_log    = (const float*)d_in[5];
    const float* dt_bias  = (const float*)d_in[6];
    const float* w_out    = (const float*)d_in[7];
    float* out = (float*)d_out;

    void *p_xnb, *p_proj, *p_hb, *p_dt, *p_la, *p_G, *p_y, *p_yb, *p_w1, *p_w2;
    cudaGetSymbolAddress(&p_xnb, g_xnb);
    cudaGetSymbolAddress(&p_proj, g_proj);
    cudaGetSymbolAddress(&p_hb,  g_hb);
    cudaGetSymbolAddress(&p_dt,  g_dt);
    cudaGetSymbolAddress(&p_la,  g_la);
    cudaGetSymbolAddress(&p_G,   g_G);
    cudaGetSymbolAddress(&p_y,   g_y);
    cudaGetSymbolAddress(&p_yb,  g_yb);
    cudaGetSymbolAddress(&p_w1,  g_wT1b);
    cudaGetSymbolAddress(&p_w2,  g_wT2b);
    __nv_bfloat16* xnb  = (__nv_bfloat16*)p_xnb;
    float*         proj = (float*)p_proj;
    __nv_bfloat16* hb   = (__nv_bfloat16*)p_hb;
    float*         dt   = (float*)p_dt;
    float*         la   = (float*)p_la;
    float*         G    = (float*)p_G;
    float*         y    = (float*)p_y;
    __nv_bfloat16* yb   = (__nv_bfloat16*)p_yb;
    __nv_bfloat16* wT1b = (__nv_bfloat16*)p_w1;
    __nv_bfloat16* wT2b = (__nv_bfloat16*)p_w2;

    // weight transposes to bf16 (K-major operands for mma B)
    transpose_bf16_kernel<<<dim3(PROJ / 32, N_EMBD / 32), dim3(32, 8)>>>(
        w_in, wT1b, N_EMBD, PROJ);
    transpose_bf16_kernel<<<dim3(N_EMBD / 32, D_INNER / 32), dim3(32, 8)>>>(
        w_out, wT2b, D_INNER, N_EMBD);

    rmsnorm_kernel<<<SEQ, 256>>>(x, nscale, xnb);

    // GEMM1: proj[512,4256] = xn @ w_in   (bf16 tensor cores)
    {
        dim3 grid((PROJ + 127) / 128, SEQ / 128);   // 34 x 4
        bf16_gemm_kernel<128, 128, 4, 2, false><<<grid, 256>>>(
            xnb, wT1b, nullptr, proj, SEQ, PROJ, N_EMBD);
    }

    conv_silu_kernel<<<(SEQ * D_INNER) / 256, 256>>>(proj, conv_w, conv_b, hb);
    dt_scan_kernel<<<N_HEADS, SEQ>>>(proj, dt_bias, A_log, dt, la);
    cbt_kernel<<<dim3(SEQ / 64, SEQ / 64), 256>>>(proj, G);
    attn_wmma_kernel<<<dim3(SEQ / 64, N_HEADS), 128>>>(G, hb, la, dt, y);
    gate_kernel<<<(SEQ * D_INNER) / 256, 256>>>(proj, y, yb);

    // GEMM2: out[512,1024] = yb @ w_out + x   (bf16 tensor cores)
    {
        dim3 grid(N_EMBD / 64, SEQ / 64);            // 16 x 8
        bf16_gemm_kernel<64, 64, 2, 2, true><<<grid, 128>>>(
            yb, wT2b, x, out, SEQ, N_EMBD, D_INNER);
    }
}

// round 5
// speedup vs baseline: 2.8908x; 1.2704x over previous
#include <cuda_runtime.h>
#include <cuda_bf16.h>
#include <mma.h>
#include <cstdint>
#include <math.h>

using namespace nvcuda;

// ---------------- problem constants ----------------
#define N_EMBD   1024
#define D_INNER  2048
#define D_STATE  64
#define N_HEADS  32
#define HEAD_DIM 64
#define D_CONV   4
#define SEQ      512
#define PROJ     4256          // 2*D_INNER + N_HEADS + 2*D_STATE
#define COL_GATE 0
#define COL_SSM  2048
#define COL_DT   4096
#define COL_B    4128
#define COL_C    4192

// ---------------- scratch (no allocation allowed) ----------------
__device__ __nv_bfloat16 g_xnb [SEQ * N_EMBD];    // bf16 rmsnorm output
__device__ float         g_proj[SEQ * PROJ];
__device__ __nv_bfloat16 g_hb  [SEQ * D_INNER];   // bf16 conv+silu output
__device__ float         g_dt  [N_HEADS * SEQ];   // [h][t]
__device__ float         g_la  [N_HEADS * SEQ];   // [h][t] cumsum A*dt
__device__ float         g_G   [SEQ * SEQ];       // C @ B^T
__device__ float         g_part[2 * SEQ * N_EMBD];// split-K partials
__device__ __nv_bfloat16 g_yb  [SEQ * D_INNER];   // gated y, bf16
__device__ __nv_bfloat16 g_w1b [N_EMBD * PROJ];   // w_in  bf16 [K][N]
__device__ __nv_bfloat16 g_w2b [D_INNER * N_EMBD];// w_out bf16 [K][N]

__device__ __forceinline__ float siluf(float v) {
    return v / (1.0f + __expf(-v));
}

__device__ __forceinline__ uint32_t smem_u32(const void* p) {
    uint32_t a;
    asm("{ .reg .u64 tmp; cvta.to.shared.u64 tmp, %1; cvt.u32.u64 %0, tmp; }"
        : "=r"(a) : "l"(p));
    return a;
}
__device__ __forceinline__ void cp_async16(uint32_t dst, const void* src) {
    asm volatile("cp.async.cg.shared.global [%0], [%1], 16;\n"
                 :: "r"(dst), "l"(src) : "memory");
}
__device__ __forceinline__ void cp_commit() {
    asm volatile("cp.async.commit_group;\n" ::: "memory");
}
template<int NN> __device__ __forceinline__ void cp_wait() {
    asm volatile("cp.async.wait_group %0;\n" :: "n"(NN) : "memory");
}

// ================= bf16 WMMA GEMM (B row-major [K][N]) =================
// Cz[M,N] = A[M, kbase:kbase+Kslice] @ B[kbase:kbase+Kslice, N]
// where kbase = blockIdx.z * Kslice, Cz = C + blockIdx.z * M * N.
// BK = 64, double-buffered cp.async, dynamic smem.
template<int BM, int BN, int WARPS_M, int WARPS_N>
__global__ void __launch_bounds__(WARPS_M * WARPS_N * 32)
bf16_gemm_kernel(const __nv_bfloat16* __restrict__ A,
                 const __nv_bfloat16* __restrict__ B,
                 float* __restrict__ C,
                 int M, int N, int Ktot, int Kslice)
{
    constexpr int THREADS = WARPS_M * WARPS_N * 32;
    constexpr int BK  = 64;
    constexpr int LDA = BK + 8;          // halves
    constexpr int LDB = BN + 8;
    constexpr int WM  = BM / WARPS_M;
    constexpr int WN  = BN / WARPS_N;
    constexpr int MF  = WM / 16;
    constexpr int NF  = WN / 16;
    constexpr int A_CH = BK / 8;         // 16B chunks per A row
    constexpr int B_CH = BN / 8;
    constexpr int A_IT = (BM * A_CH) / THREADS;
    constexpr int B_IT = (BK * B_CH) / THREADS;

    extern __shared__ __nv_bfloat16 dsm[];
    __nv_bfloat16* As = dsm;                    // [2][BM][LDA]
    __nv_bfloat16* Bs = dsm + 2 * BM * LDA;     // [2][BK][LDB]

    const int tid = threadIdx.x;
    const int wid = tid >> 5;
    const int wy  = wid / WARPS_N;
    const int wx  = wid % WARPS_N;
    const int bm  = blockIdx.y * BM;
    const int bn  = blockIdx.x * BN;
    const int kbase = blockIdx.z * Kslice;
    float* Cz = C + (size_t)blockIdx.z * M * N;

    wmma::fragment<wmma::accumulator, 16, 16, 16, float> acc[MF][NF];
    #pragma unroll
    for (int i = 0; i < MF; i++)
        #pragma unroll
        for (int j = 0; j < NF; j++)
            wmma::fill_fragment(acc[i][j], 0.0f);

    auto load_stage = [&](int i, int s) {
        int k0 = kbase + i * BK;
        uint32_t zero = 0;
        #pragma unroll
        for (int l = 0; l < A_IT; l++) {
            int idx = tid + l * THREADS;
            int row = idx / A_CH;
            int c8  = (idx % A_CH) * 8;
            cp_async16(smem_u32(As + (size_t)s * BM * LDA + row * LDA + c8),
                       A + (size_t)(bm + row) * Ktot + k0 + c8);
        }
        #pragma unroll
        for (int l = 0; l < B_IT; l++) {
            int idx = tid + l * THREADS;
            int row = idx / B_CH;
            int c8  = (idx % B_CH) * 8;
            uint32_t dst = smem_u32(Bs + (size_t)s * BK * LDB + row * LDB + c8);
            if (bn + c8 < N)
                cp_async16(dst, B + (size_t)(k0 + row) * N + bn + c8);
            else
                asm volatile("st.shared.v4.b32 [%0], {%1,%1,%1,%1};"
                             :: "r"(dst), "r"(zero) : "memory");
        }
        cp_commit();
    };

    const int NC = Kslice / BK;
    load_stage(0, 0);

    for (int i = 0; i < NC; i++) {
        int s = i & 1;
        if (i + 1 < NC) {
            load_stage(i + 1, s ^ 1);
            cp_wait<1>();
        } else {
            cp_wait<0>();
        }
        __syncthreads();

        const __nv_bfloat16* Asb = As + (size_t)s * BM * LDA;
        const __nv_bfloat16* Bsb = Bs + (size_t)s * BK * LDB;
        #pragma unroll
        for (int kk = 0; kk < BK; kk += 16) {
            wmma::fragment<wmma::matrix_a, 16, 16, 16,
                           __nv_bfloat16, wmma::row_major> af[MF];
            wmma::fragment<wmma::matrix_b, 16, 16, 16,
                           __nv_bfloat16, wmma::row_major> bf[NF];
            #pragma unroll
            for (int m = 0; m < MF; m++)
                wmma::load_matrix_sync(af[m],
                    Asb + (wy * WM + m * 16) * LDA + kk, LDA);
            #pragma unroll
            for (int n = 0; n < NF; n++)
                wmma::load_matrix_sync(bf[n],
                    Bsb + kk * LDB + wx * WN + n * 16, LDB);
            #pragma unroll
            for (int m = 0; m < MF; m++)
                #pragma unroll
                for (int n = 0; n < NF; n++)
                    wmma::mma_sync(acc[m][n], af[m], bf[n], acc[m][n]);
        }
        __syncthreads();
    }

    #pragma unroll
    for (int m = 0; m < MF; m++) {
        int row0 = bm + wy * WM + m * 16;
        #pragma unroll
        for (int n = 0; n < NF; n++) {
            int col0 = bn + wx * WN + n * 16;
            if (col0 < N)
                wmma::store_matrix_sync(&Cz[(size_t)row0 * N + col0],
                                        acc[m][n], N, wmma::mem_row_major);
        }
    }
}

// ---------------- fp32 -> bf16 streaming cast ----------------
__global__ void cast_bf16_kernel(const float* __restrict__ in,
                                 __nv_bfloat16* __restrict__ out, int n4) {
    int i = blockIdx.x * blockDim.x + threadIdx.x;
    if (i >= n4) return;
    float4 v = reinterpret_cast<const float4*>(in)[i];
    __nv_bfloat162 a = __floats2bfloat162_rn(v.x, v.y);
    __nv_bfloat162 b = __floats2bfloat162_rn(v.z, v.w);
    uint2 pk;
    pk.x = *reinterpret_cast<uint32_t*>(&a);
    pk.y = *reinterpret_cast<uint32_t*>(&b);
    reinterpret_cast<uint2*>(out)[i] = pk;
}

// ---------------- RMSNorm (bf16 output) ----------------
__global__ void rmsnorm_kernel(const float* __restrict__ x,
                               const float* __restrict__ scale,
                               __nv_bfloat16* __restrict__ out) {
    int row = blockIdx.x;
    int tid = threadIdx.x;              // 256 threads, 1 float4 each
    const float4* xr = reinterpret_cast<const float4*>(x + row * N_EMBD);
    float4 v = xr[tid];
    float ss = v.x * v.x + v.y * v.y + v.z * v.z + v.w * v.w;
    #pragma unroll
    for (int o = 16; o; o >>= 1) ss += __shfl_xor_sync(0xffffffffu, ss, o);
    __shared__ float wsum[8];
    int lane = tid & 31, wid = tid >> 5;
    if (lane == 0) wsum[wid] = ss;
    __syncthreads();
    __shared__ float s_inv;
    if (tid == 0) {
        float tot = 0.f;
        #pragma unroll
        for (int i = 0; i < 8; i++) tot += wsum[i];
        s_inv = rsqrtf(tot / (float)N_EMBD + 1e-6f);
    }
    __syncthreads();
    float inv = s_inv;
    const float4 sc = reinterpret_cast<const float4*>(scale)[tid];
    __nv_bfloat162 o01 = __floats2bfloat162_rn(v.x * inv * sc.x, v.y * inv * sc.y);
    __nv_bfloat162 o23 = __floats2bfloat162_rn(v.z * inv * sc.z, v.w * inv * sc.w);
    uint2 pk;
    pk.x = *reinterpret_cast<uint32_t*>(&o01);
    pk.y = *reinterpret_cast<uint32_t*>(&o23);
    *reinterpret_cast<uint2*>(out + row * N_EMBD + tid * 4) = pk;
}

// ---------------- causal depthwise conv (4 taps) + SiLU -> bf16 ------------
__global__ void conv_silu_kernel(const float* __restrict__ proj,
                                 const float* __restrict__ w,
                                 const float* __restrict__ bias,
                                 __nv_bfloat16* __restrict__ h) {
    int i = blockIdx.x * blockDim.x + threadIdx.x;   // SEQ*D_INNER
    int t = i >> 11;
    int c = i & (D_INNER - 1);
    float acc = bias[c];
    #pragma unroll
    for (int k = 0; k < D_CONV; k++) {
        int s = t + k - (D_CONV - 1);
        if (s >= 0)
            acc += w[k * D_INNER + c] * proj[(size_t)s * PROJ + COL_SSM + c];
    }
    h[i] = __float2bfloat16(siluf(acc));
}

// ---------------- dt + la (warp-per-head scan) ----------------
__global__ void dt_scan_kernel(const float* __restrict__ proj,
                               const float* __restrict__ dt_bias,
                               const float* __restrict__ A_log,
                               float* __restrict__ dt_out,
                               float* __restrict__ la_out) {
    int head = blockIdx.x * 8 + (threadIdx.x >> 5);
    int lane = threadIdx.x & 31;
    float bias = dt_bias[head];
    float A = -expf(A_log[head]);

    float vals[16];
    float run = 0.f;
    #pragma unroll
    for (int i = 0; i < 16; i++) {
        int t = lane * 16 + i;
        float z = proj[(size_t)t * PROJ + COL_DT + head] + bias;
        float d = (z > 20.f) ? z : log1pf(__expf(z));
        dt_out[head * SEQ + t] = d;
        run += A * d;
        vals[i] = run;
    }
    // inclusive shfl scan of per-lane totals -> exclusive prefix
    float tot = run;
    #pragma unroll
    for (int off = 1; off < 32; off <<= 1) {
        float nb = __shfl_up_sync(0xffffffffu, tot, off);
        if (lane >= off) tot += nb;
    }
    float excl = tot - run;
    #pragma unroll
    for (int i = 0; i < 16; i++)
        la_out[head * SEQ + lane * 16 + i] = vals[i] + excl;
}

// ---------------- G = C @ B^T (512x512, K=64) ----------------
__global__ void cbt_kernel(const float* __restrict__ proj,
                           float* __restrict__ G) {
    __shared__ float Csh[D_STATE][64 + 1];
    __shared__ float Bsh[D_STATE][64 + 1];
    int tid = threadIdx.x;                   // 256
    int t0 = blockIdx.y * 64;
    int s0 = blockIdx.x * 64;

    #pragma unroll
    for (int l = 0; l < 16; l++) {
        int idx = tid + l * 256;
        int r = idx >> 6;
        int n = idx & 63;
        Csh[n][r] = proj[(size_t)(t0 + r) * PROJ + COL_C + n];
        Bsh[n][r] = proj[(size_t)(s0 + r) * PROJ + COL_B + n];
    }
    __syncthreads();

    int ty = tid / 16, tx = tid % 16;
    int r0 = ty * 4, c0 = tx * 4;
    float acc[4][4];
    #pragma unroll
    for (int i = 0; i < 4; i++)
        #pragma unroll
        for (int j = 0; j < 4; j++) acc[i][j] = 0.f;

    #pragma unroll
    for (int k = 0; k < D_STATE; k++) {
        float ra[4], rb[4];
        #pragma unroll
        for (int i = 0; i < 4; i++) ra[i] = Csh[k][r0 + i];
        #pragma unroll
        for (int j = 0; j < 4; j++) rb[j] = Bsh[k][c0 + j];
        #pragma unroll
        for (int i = 0; i < 4; i++)
            #pragma unroll
            for (int j = 0; j < 4; j++) acc[i][j] += ra[i] * rb[j];
    }
    #pragma unroll
    for (int i = 0; i < 4; i++)
        #pragma unroll
        for (int j = 0; j < 4; j++)
            G[(size_t)(t0 + r0 + i) * SEQ + s0 + c0 + j] = acc[i][j];
}

// ---------------- SSM attention (bf16 WMMA) + fused gate -> bf16 ----------
// y[t,h,p] = sum_{s<=t} exp(la[t]-la[s]) * dt[s] * G[t,s] * h[s, head*64+p]
// yb = bf16(y * silu(gate))
__global__ void __launch_bounds__(256)
attn_gate_kernel(const float* __restrict__ G,
                 const __nv_bfloat16* __restrict__ hb,
                 const float* __restrict__ la,
                 const float* __restrict__ dt,
                 const float* __restrict__ proj,
                 __nv_bfloat16* __restrict__ yb) {
    const int ti   = blockIdx.x;
    const int head = blockIdx.y;
    const int t0   = ti * 64;
    const int tid  = threadIdx.x;   // 256 threads, 8 warps
    const int wid  = tid >> 5;
    const int wy   = wid >> 1;      // 0..3  (16-row strip)
    const int wx   = wid & 1;       // 0..1  (32-col strip)

    __shared__ __nv_bfloat16 Ws[64][72];   // W[t][s]
    __shared__ __nv_bfloat16 Xs[64][72];   // X[s][p]
    __shared__ float Ys[64][68];           // fp32 result tile
    __shared__ float la_t[64], la_s[64], dt_s[64];

    if (tid < 64) la_t[tid] = la[head * SEQ + t0 + tid];

    wmma::fragment<wmma::accumulator, 16, 16, 16, float> acc[2];
    wmma::fill_fragment(acc[0], 0.0f);
    wmma::fill_fragment(acc[1], 0.0f);

    for (int si = 0; si <= ti; si++) {
        int s0 = si * 64;
        __syncthreads();   // protect smem from previous iteration's readers
        if (tid < 64) {
            la_s[tid] = la[head * SEQ + s0 + tid];
            dt_s[tid] = dt[head * SEQ + s0 + tid];
        }
        // X tile: 64x64 bf16 (8B vector loads)
        #pragma unroll
        for (int l = 0; l < 4; l++) {
            int idx = tid + l * 256;
            int sl = idx >> 4, c = idx & 15;
            *reinterpret_cast<uint2*>(&Xs[sl][c * 4]) =
                *reinterpret_cast<const uint2*>(
                    &hb[(size_t)(s0 + sl) * D_INNER + head * HEAD_DIM + c * 4]);
        }
        __syncthreads();
        // W tile build (fp32 math, bf16 store)
        #pragma unroll
        for (int l = 0; l < 16; l++) {
            int idx = tid + l * 256;
            int tl = idx >> 6, sl = idx & 63;
            float w = 0.f;
            if (s0 + sl <= t0 + tl) {
                float g = G[(size_t)(t0 + tl) * SEQ + s0 + sl];
                w = g * __expf(la_t[tl] - la_s[sl]) * dt_s[sl];
            }
            Ws[tl][sl] = __float2bfloat16(w);
        }
        __syncthreads();
        #pragma unroll
        for (int ks = 0; ks < 4; ks++) {
            wmma::fragment<wmma::matrix_a, 16, 16, 16,
                           __nv_bfloat16, wmma::row_major> af;
            wmma::load_matrix_sync(af, &Ws[wy * 16][ks * 16], 72);
            #pragma unroll
            for (int n = 0; n < 2; n++) {
                wmma::fragment<wmma::matrix_b, 16, 16, 16,
                               __nv_bfloat16, wmma::row_major> bf;
                wmma::load_matrix_sync(bf, &Xs[ks * 16][wx * 32 + n * 16], 72);
                wmma::mma_sync(acc[n], af, bf, acc[n]);
            }
        }
    }

    // fused gate epilogue
    __syncthreads();
    #pragma unroll
    for (int n = 0; n < 2; n++)
        wmma::store_matrix_sync(&Ys[wy * 16][wx * 32 + n * 16], acc[n],
                                68, wmma::mem_row_major);
    __syncthreads();
    #pragma unroll
    for (int l = 0; l < 16; l++) {
        int idx = tid + l * 256;
        int row = idx >> 6, col = idx & 63;
        float g = proj[(size_t)(t0 + row) * PROJ + COL_GATE + head * HEAD_DIM + col];
        yb[(size_t)(t0 + row) * D_INNER + head * HEAD_DIM + col] =
            __float2bfloat16(Ys[row][col] * siluf(g));
    }
}

// ---------------- combine: out = x + p0 + p1 ----------------
__global__ void combine_kernel(const float* __restrict__ x,
                               const float* __restrict__ part,
                               float* __restrict__ out) {
    int i = blockIdx.x * blockDim.x + threadIdx.x;   // SEQ*N_EMBD/4
    float4 a = reinterpret_cast<const float4*>(x)[i];
    float4 p = reinterpret_cast<const float4*>(part)[i];
    float4 q = reinterpret_cast<const float4*>(part + SEQ * N_EMBD)[i];
    a.x += p.x + q.x;  a.y += p.y + q.y;
    a.z += p.z + q.z;  a.w += p.w + q.w;
    reinterpret_cast<float4*>(out)[i] = a;
}

// ---------------- host launch ----------------
#define G1_SMEM (2 * 128 * 72 * 2 + 2 * 64 * 136 * 2)   // 71680
#define G2_SMEM (2 * 64 * 72 * 2 + 2 * 64 * 72 * 2)     // 36864

extern "C" void kernel_launch(void* const* d_in, const int* in_sizes, int n_in,
                              void* d_out, int out_size) {
    const float* x        = (const float*)d_in[0];
    const float* nscale   = (const float*)d_in[1];
    const float* w_in     = (const float*)d_in[2];
    const float* conv_w   = (const float*)d_in[3];
    const float* conv_b   = (const float*)d_in[4];
    const float* A_log    = (const float*)d_in[5];
    const float* dt_bias  = (const float*)d_in[6];
    const float* w_out    = (const float*)d_in[7];
    float* out = (float*)d_out;

    void *p_xnb, *p_proj, *p_hb, *p_dt, *p_la, *p_G, *p_part, *p_yb, *p_w1, *p_w2;
    cudaGetSymbolAddress(&p_xnb,  g_xnb);
    cudaGetSymbolAddress(&p_proj, g_proj);
    cudaGetSymbolAddress(&p_hb,   g_hb);
    cudaGetSymbolAddress(&p_dt,   g_dt);
    cudaGetSymbolAddress(&p_la,   g_la);
    cudaGetSymbolAddress(&p_G,    g_G);
    cudaGetSymbolAddress(&p_part, g_part);
    cudaGetSymbolAddress(&p_yb,   g_yb);
    cudaGetSymbolAddress(&p_w1,   g_w1b);
    cudaGetSymbolAddress(&p_w2,   g_w2b);
    __nv_bfloat16* xnb  = (__nv_bfloat16*)p_xnb;
    float*         proj = (float*)p_proj;
    __nv_bfloat16* hb   = (__nv_bfloat16*)p_hb;
    float*         dt   = (float*)p_dt;
    float*         la   = (float*)p_la;
    float*         G    = (float*)p_G;
    float*         part = (float*)p_part;
    __nv_bfloat16* ybuf = (__nv_bfloat16*)p_yb;
    __nv_bfloat16* w1b  = (__nv_bfloat16*)p_w1;
    __nv_bfloat16* w2b  = (__nv_bfloat16*)p_w2;

    cudaFuncSetAttribute(bf16_gemm_kernel<128, 128, 4, 2>,
        cudaFuncAttributeMaxDynamicSharedMemorySize, G1_SMEM);
    cudaFuncSetAttribute(bf16_gemm_kernel<64, 64, 2, 2>,
        cudaFuncAttributeMaxDynamicSharedMemorySize, G2_SMEM);

    // weight casts fp32 -> bf16 (keep [K][N] row-major)
    cast_bf16_kernel<<<(N_EMBD * PROJ / 4 + 255) / 256, 256>>>(
        w_in, w1b, N_EMBD * PROJ / 4);
    cast_bf16_kernel<<<(D_INNER * N_EMBD / 4 + 255) / 256, 256>>>(
        w_out, w2b, D_INNER * N_EMBD / 4);

    rmsnorm_kernel<<<SEQ, 256>>>(x, nscale, xnb);

    // GEMM1: proj[512,4256] = xn @ w_in
    {
        dim3 grid((PROJ + 127) / 128, SEQ / 128, 1);   // 34 x 4
        bf16_gemm_kernel<128, 128, 4, 2><<<grid, 256, G1_SMEM>>>(
            xnb, w1b, proj, SEQ, PROJ, N_EMBD, N_EMBD);
    }

    conv_silu_kernel<<<(SEQ * D_INNER) / 256, 256>>>(proj, conv_w, conv_b, hb);
    dt_scan_kernel<<<N_HEADS / 8, 256>>>(proj, dt_bias, A_log, dt, la);
    cbt_kernel<<<dim3(SEQ / 64, SEQ / 64), 256>>>(proj, G);
    attn_gate_kernel<<<dim3(SEQ / 64, N_HEADS), 256>>>(G, hb, la, dt, proj, ybuf);

    // GEMM2 (split-K=2): part[z] = yb[:, z*1024:(z+1)*1024] @ w_out[z...]
    {
        dim3 grid(N_EMBD / 64, SEQ / 64, 2);           // 16 x 8 x 2
        bf16_gemm_kernel<64, 64, 2, 2><<<grid, 128, G2_SMEM>>>(
            ybuf, w2b, part, SEQ, N_EMBD, D_INNER, D_INNER / 2);
    }

    combine_kernel<<<(SEQ * N_EMBD / 4) / 256, 256>>>(x, part, out);
}